// round 13
// baseline (speedup 1.0000x reference)
#include <cuda_runtime.h>
#include <cuda_fp16.h>
#include <math.h>
#include <stdint.h>

#define T_TOK 32768
#define DIM   128
#define KC    8192
#define BM    128
#define NT    64
#define ITERS (KC / NT)          /* 128 */
#define GRID_GEMM (T_TOK / BM)   /* 256 */
#define TILE_BYTES 16384
#define SO_RING 32768            /* A-stash occupies [0,32KB) */
#define SMEM_GEMM (SO_RING + 2 * TILE_BYTES)   /* 64KB */
#define PAD 132
#define SMEM_PROJ (2 * 128 * PAD * 4)

/* ---------------- device scratch (no allocations) ---------------- */
__device__ __align__(16) unsigned char g_cbt[ITERS * TILE_BYTES]; /* 2MB fp16 B frags */
__device__ float  g_codebook[KC * DIM];
__device__ __align__(16) float g_cnorm[KC];
__device__ int    g_counts[KC];
__device__ double g_ssep[GRID_GEMM];
__device__ unsigned int g_done;

__device__ __forceinline__ uint32_t smem_u32(const void* p) {
    uint32_t a;
    asm("{ .reg .u64 t; cvta.to.shared.u64 t, %1; cvt.u32.u64 %0, t; }"
        : "=r"(a) : "l"(p));
    return a;
}

#define CP16(dst, src) \
    asm volatile("cp.async.cg.shared.global [%0], [%1], 16;" :: "r"((uint32_t)(dst)), "l"(src))
#define CP_COMMIT() asm volatile("cp.async.commit_group;" ::: "memory")
#define CP_WAIT0()  asm volatile("cp.async.wait_group 0;"  ::: "memory")

#define MMA_F16(d, a0, a1, a2, a3, b0, b1) \
    asm volatile("mma.sync.aligned.m16n8k16.row.col.f32.f16.f16.f32 " \
                 "{%0,%1,%2,%3}, {%4,%5,%6,%7}, {%8,%9}, {%0,%1,%2,%3};" \
                 : "+f"((d)[0]), "+f"((d)[1]), "+f"((d)[2]), "+f"((d)[3]) \
                 : "r"(a0), "r"(a1), "r"(a2), "r"(a3), \
                   "r"(b0), "r"(b1))

#define INS4(tv0, tv1, tv2, tv3, ti0, ti1, ti2, ti3, v, n) do {               \
    if ((v) < (tv3)) {                                                        \
        if ((v) < (tv2)) {                                                    \
            tv3 = tv2; ti3 = ti2;                                             \
            if ((v) < (tv1)) {                                                \
                tv2 = tv1; ti2 = ti1;                                         \
                if ((v) < (tv0)) { tv1 = tv0; ti1 = ti0; tv0 = (v); ti0 = (n); } \
                else             { tv1 = (v); ti1 = (n); }                    \
            } else { tv2 = (v); ti2 = (n); }                                  \
        } else { tv3 = (v); ti3 = (n); }                                      \
    }                                                                         \
} while (0)

/* ---------------- projection GEMM: C = emb @ W^T + b (128 codes/block) ----------------
   Emits fp32 codebook, cnorm, fp16 packed B fragments; zeroes g_counts and g_done.
   Packed layout per 64-code tile (16KB): [nblk(8)][kblk(8)][lane(32)] x 8B,
   8B = {h(k), h(k+1), h(k+8), h(k+9)}, lane = nl*4 + ksub,
   n = tile*64 + nblk*8 + nl, k = kblk*16 + regsel*8 + ksub*2 + par */
__global__ __launch_bounds__(256, 1)
void k_proj(const float* __restrict__ emb,
            const float* __restrict__ pw,
            const float* __restrict__ pbias) {
    extern __shared__ float ps[];
    float* es = ps;
    float* wsm = ps + 128 * PAD;
    const int tid = threadIdx.x;
    const int tx = tid & 15, ty = tid >> 4;
    const int c0 = blockIdx.x * 128;

    if (tid < 128) g_counts[c0 + tid] = 0;
    if (blockIdx.x == 0 && tid == 0) g_done = 0;

#pragma unroll
    for (int i = 0; i < 16; i++) {
        int f = tid + i * 256;
        int row = f >> 5;
        int c4 = f & 31;
        int sw = (((row >> 2) ^ (c4 & 7)) << 2) | (row & 3);
        float4 v = *((const float4*)(emb + (size_t)(c0 + row) * DIM) + c4);
        es[(4 * c4 + 0) * PAD + sw] = v.x;
        es[(4 * c4 + 1) * PAD + sw] = v.y;
        es[(4 * c4 + 2) * PAD + sw] = v.z;
        es[(4 * c4 + 3) * PAD + sw] = v.w;
        float4 w = *((const float4*)(pw + (size_t)row * DIM) + c4);
        wsm[(4 * c4 + 0) * PAD + sw] = w.x;
        wsm[(4 * c4 + 1) * PAD + sw] = w.y;
        wsm[(4 * c4 + 2) * PAD + sw] = w.z;
        wsm[(4 * c4 + 3) * PAD + sw] = w.w;
    }
    __syncthreads();

    float acc[8][8];
#pragma unroll
    for (int im = 0; im < 8; im++)
#pragma unroll
        for (int jn = 0; jn < 8; jn++) acc[im][jn] = 0.0f;

#pragma unroll 4
    for (int k = 0; k < 128; k++) {
        int s = (k >> 2) & 7;
        const float* er = es + k * PAD;
        const float* wr = wsm + k * PAD;
        float4 a0 = *(const float4*)(er + ((ty ^ s) << 2));
        float4 a1 = *(const float4*)(er + 64 + ((ty ^ s) << 2));
        float4 b0 = *(const float4*)(wr + ((tx ^ s) << 2));
        float4 b1 = *(const float4*)(wr + 64 + ((tx ^ s) << 2));
        float a[8] = {a0.x, a0.y, a0.z, a0.w, a1.x, a1.y, a1.z, a1.w};
        float b[8] = {b0.x, b0.y, b0.z, b0.w, b1.x, b1.y, b1.z, b1.w};
#pragma unroll
        for (int im = 0; im < 8; im++)
#pragma unroll
            for (int jn = 0; jn < 8; jn++)
                acc[im][jn] = fmaf(a[im], b[jn], acc[im][jn]);
    }

    float cnp[8];
#pragma unroll
    for (int im = 0; im < 8; im++) cnp[im] = 0.0f;

#pragma unroll
    for (int im = 0; im < 8; im++) {
        int cl = (im < 4) ? (ty * 4 + im) : (64 + ty * 4 + im - 4);
        int cg = c0 + cl;
        int tile = cg >> 6, nblk = (cg >> 3) & 7, nl = cg & 7;
#pragma unroll
        for (int jn = 0; jn < 8; jn++) {
            int d = (jn < 4) ? (tx * 4 + jn) : (64 + tx * 4 + jn - 4);
            float val = acc[im][jn] + pbias[d];
            g_codebook[(size_t)cg * DIM + d] = val;
            cnp[im] = fmaf(val, val, cnp[im]);
            int kblk = d >> 4, kin = d & 15;
            int regsel = kin >> 3, ksub = (kin & 7) >> 1, par = kin & 1;
            int lane = nl * 4 + ksub;
            size_t off = (size_t)tile * TILE_BYTES + nblk * 2048 + kblk * 256
                       + lane * 8 + regsel * 4 + par * 2;
            *(__half*)(g_cbt + off) = __float2half_rn(val);
        }
    }
#pragma unroll
    for (int im = 0; im < 8; im++) {
#pragma unroll
        for (int o = 8; o > 0; o >>= 1)
            cnp[im] += __shfl_xor_sync(0xffffffffu, cnp[im], o, 16);
    }
    if (tx == 0) {
#pragma unroll
        for (int im = 0; im < 8; im++) {
            int cl = (im < 4) ? (ty * 4 + im) : (64 + ty * 4 + im - 4);
            g_cnorm[c0 + cl] = cnp[im];
        }
    }
}

/* ---------------- fused: fp16 HMMA GEMM + top-4 + exact rescore + loss ----------------
   A fragments live in smem (thread-private stash) -> regs ~85 -> 3 CTAs/SM. */
__global__ __launch_bounds__(256, 3)
void k_gemm(const float* __restrict__ z, float* __restrict__ out) {
    extern __shared__ unsigned char smem[];
    const uint32_t sb = smem_u32(smem);
    const int tid = threadIdx.x;
    const int lane = tid & 31;
    const int warp = tid >> 5;
    const int r = lane >> 2;
    const int cc = lane & 3;
    const int m0 = blockIdx.x * BM;

    /* prologue: prefetch B tile 0 into ring slot 0 */
#pragma unroll
    for (int j = 0; j < 4; j++) {
        uint32_t off = (uint32_t)(tid + j * 256) * 16;
        CP16(sb + SO_RING + off, g_cbt + off);
    }
    CP_COMMIT();

    /* A fragments (fp16): build in regs, stash to smem (thread-private; no sync needed).
       Layout: [warp(8)][kb(8)][lane(32)] x 16B */
    const uint32_t aBase = sb + warp * 4096 + lane * 16;
    {
        const float* z0 = z + (size_t)(m0 + warp * 16 + r) * DIM;
#pragma unroll
        for (int kb = 0; kb < 8; kb++) {
            uint32_t aq[4];
#pragma unroll
            for (int q = 0; q < 4; q++) {
                const float* src = z0 + ((q & 1) ? 8 * DIM : 0) + kb * 16 + (q >> 1) * 8 + cc * 2;
                float2 v = *(const float2*)src;
                __half2 hh = __floats2half2_rn(v.x, v.y);
                aq[q] = *(uint32_t*)&hh;
            }
            asm volatile("st.shared.v4.b32 [%0],{%1,%2,%3,%4};"
                         :: "r"(aBase + kb * 512), "r"(aq[0]), "r"(aq[1]), "r"(aq[2]), "r"(aq[3]));
        }
    }

    float av0 = 3.4e38f, av1 = 3.4e38f, av2 = 3.4e38f, av3 = 3.4e38f;
    float bv0 = 3.4e38f, bv1 = 3.4e38f, bv2 = 3.4e38f, bv3 = 3.4e38f;
    int ai0 = 0, ai1 = 0, ai2 = 0, ai3 = 0;
    int bi0 = 0, bi1 = 0, bi2 = 0, bi3 = 0;

    for (int i = 0; i < ITERS; i++) {
        CP_WAIT0();
        __syncthreads();
        if (i + 1 < ITERS) {
            const unsigned char* src = g_cbt + (size_t)(i + 1) * TILE_BYTES;
            uint32_t dst = sb + SO_RING + ((i + 1) & 1) * TILE_BYTES;
#pragma unroll
            for (int j = 0; j < 4; j++) {
                uint32_t off = (uint32_t)(tid + j * 256) * 16;
                CP16(dst + off, src + off);
            }
            CP_COMMIT();
        }

        float acc[8][4];
#pragma unroll
        for (int nb = 0; nb < 8; nb++)
#pragma unroll
            for (int q = 0; q < 4; q++) acc[nb][q] = 0.0f;

        const uint32_t bbase = sb + SO_RING + (i & 1) * TILE_BYTES + lane * 8;
        uint32_t a0, a1, a2, a3;
        asm volatile("ld.shared.v4.b32 {%0,%1,%2,%3},[%4];"
                     : "=r"(a0), "=r"(a1), "=r"(a2), "=r"(a3) : "r"(aBase));
#pragma unroll
        for (int kb = 0; kb < 8; kb++) {
            uint32_t n0, n1, n2, n3;
            if (kb < 7) {
                asm volatile("ld.shared.v4.b32 {%0,%1,%2,%3},[%4];"
                             : "=r"(n0), "=r"(n1), "=r"(n2), "=r"(n3)
                             : "r"(aBase + (kb + 1) * 512));
            } else { n0 = a0; n1 = a1; n2 = a2; n3 = a3; }
#pragma unroll
            for (int nb = 0; nb < 8; nb++) {
                uint32_t b0, b1;
                asm volatile("ld.shared.v2.b32 {%0,%1},[%2];"
                             : "=r"(b0), "=r"(b1) : "r"(bbase + nb * 2048 + kb * 256));
                MMA_F16(acc[nb], a0, a1, a2, a3, b0, b1);
            }
            a0 = n0; a1 = n1; a2 = n2; a3 = n3;
        }

        const int n0i = i * 64;
#pragma unroll
        for (int nb = 0; nb < 8; nb++) {
            int n = n0i + nb * 8 + cc * 2;
            float2 cn = *(const float2*)(g_cnorm + n);
            float s0 = fmaf(-2.0f, acc[nb][0], cn.x);
            float s1 = fmaf(-2.0f, acc[nb][1], cn.y);
            float s2 = fmaf(-2.0f, acc[nb][2], cn.x);
            float s3 = fmaf(-2.0f, acc[nb][3], cn.y);
            INS4(av0, av1, av2, av3, ai0, ai1, ai2, ai3, s0, n);
            INS4(av0, av1, av2, av3, ai0, ai1, ai2, ai3, s1, n + 1);
            INS4(bv0, bv1, bv2, bv3, bi0, bi1, bi2, bi3, s2, n);
            INS4(bv0, bv1, bv2, bv3, bi0, bi1, bi2, bi3, s3, n + 1);
        }
    }

    /* merge top-4 across the 4 cc lanes */
#pragma unroll
    for (int off = 1; off <= 2; off <<= 1) {
        float wa0 = __shfl_xor_sync(0xffffffffu, av0, off);
        float wa1 = __shfl_xor_sync(0xffffffffu, av1, off);
        float wa2 = __shfl_xor_sync(0xffffffffu, av2, off);
        float wa3 = __shfl_xor_sync(0xffffffffu, av3, off);
        int ja0 = __shfl_xor_sync(0xffffffffu, ai0, off);
        int ja1 = __shfl_xor_sync(0xffffffffu, ai1, off);
        int ja2 = __shfl_xor_sync(0xffffffffu, ai2, off);
        int ja3 = __shfl_xor_sync(0xffffffffu, ai3, off);
        float wb0 = __shfl_xor_sync(0xffffffffu, bv0, off);
        float wb1 = __shfl_xor_sync(0xffffffffu, bv1, off);
        float wb2 = __shfl_xor_sync(0xffffffffu, bv2, off);
        float wb3 = __shfl_xor_sync(0xffffffffu, bv3, off);
        int jb0 = __shfl_xor_sync(0xffffffffu, bi0, off);
        int jb1 = __shfl_xor_sync(0xffffffffu, bi1, off);
        int jb2 = __shfl_xor_sync(0xffffffffu, bi2, off);
        int jb3 = __shfl_xor_sync(0xffffffffu, bi3, off);
        INS4(av0, av1, av2, av3, ai0, ai1, ai2, ai3, wa0, ja0);
        INS4(av0, av1, av2, av3, ai0, ai1, ai2, ai3, wa1, ja1);
        INS4(av0, av1, av2, av3, ai0, ai1, ai2, ai3, wa2, ja2);
        INS4(av0, av1, av2, av3, ai0, ai1, ai2, ai3, wa3, ja3);
        INS4(bv0, bv1, bv2, bv3, bi0, bi1, bi2, bi3, wb0, jb0);
        INS4(bv0, bv1, bv2, bv3, bi0, bi1, bi2, bi3, wb1, jb1);
        INS4(bv0, bv1, bv2, bv3, bi0, bi1, bi2, bi3, wb2, jb2);
        INS4(bv0, bv1, bv2, bv3, bi0, bi1, bi2, bi3, wb3, jb3);
    }

    /* ---- fused rescore: stash candidates in smem (A-stash region reusable) ---- */
    CP_WAIT0();
    __syncthreads();
    int4*  scand = (int4*)smem;
    float* swsq  = (float*)(smem + 2048);
    int*   sflag = (int*)(smem + 2048 + 32);
    if (cc == 0) {
        scand[warp * 16 + r]     = make_int4(ai0, ai1, ai2, ai3);
        scand[warp * 16 + r + 8] = make_int4(bi0, bi1, bi2, bi3);
    }
    __syncthreads();

    float warp_sq = 0.0f;
    for (int j = 0; j < 16; j++) {
        const int tl = warp * 16 + j;
        const int t = m0 + tl;
        int4 cd = scand[tl];
        float4 zv = ((const float4*)(z + (size_t)t * DIM))[lane];
        float4 c0 = ((const float4*)(g_codebook + (size_t)cd.x * DIM))[lane];
        float4 c1 = ((const float4*)(g_codebook + (size_t)cd.y * DIM))[lane];
        float4 c2 = ((const float4*)(g_codebook + (size_t)cd.z * DIM))[lane];
        float4 c3 = ((const float4*)(g_codebook + (size_t)cd.w * DIM))[lane];
        float d0 = zv.x * c0.x + zv.y * c0.y + zv.z * c0.z + zv.w * c0.w;
        float d1 = zv.x * c1.x + zv.y * c1.y + zv.z * c1.z + zv.w * c1.w;
        float d2 = zv.x * c2.x + zv.y * c2.y + zv.z * c2.z + zv.w * c2.w;
        float d3 = zv.x * c3.x + zv.y * c3.y + zv.z * c3.z + zv.w * c3.w;
#pragma unroll
        for (int o = 16; o > 0; o >>= 1) {
            d0 += __shfl_xor_sync(0xffffffffu, d0, o);
            d1 += __shfl_xor_sync(0xffffffffu, d1, o);
            d2 += __shfl_xor_sync(0xffffffffu, d2, o);
            d3 += __shfl_xor_sync(0xffffffffu, d3, o);
        }
        float s0 = g_cnorm[cd.x] - 2.0f * d0;
        float s1 = g_cnorm[cd.y] - 2.0f * d1;
        float s2 = g_cnorm[cd.z] - 2.0f * d2;
        float s3 = g_cnorm[cd.w] - 2.0f * d3;

        float bs = s0; int bi = cd.x; float4 c = c0;
        if (s1 < bs || (s1 == bs && cd.y < bi)) { bs = s1; bi = cd.y; c = c1; }
        if (s2 < bs || (s2 == bs && cd.z < bi)) { bs = s2; bi = cd.z; c = c2; }
        if (s3 < bs || (s3 == bs && cd.w < bi)) { bs = s3; bi = cd.w; c = c3; }

        float dx = c.x - zv.x, dy = c.y - zv.y, dz = c.z - zv.z, dw = c.w - zv.w;
        float4 o4;
        o4.x = zv.x + dx; o4.y = zv.y + dy; o4.z = zv.z + dz; o4.w = zv.w + dw;
        ((float4*)(out + (size_t)t * DIM))[lane] = o4;

        float sq = dx * dx + dy * dy + dz * dz + dw * dw;
#pragma unroll
        for (int o = 16; o > 0; o >>= 1) sq += __shfl_xor_sync(0xffffffffu, sq, o);
        warp_sq += sq;
        if (lane == 0) atomicAdd(&g_counts[bi], 1);
    }
    if (lane == 0) swsq[warp] = warp_sq;
    __syncthreads();
    if (tid == 0) {
        double s = 0.0;
#pragma unroll
        for (int i = 0; i < 8; i++) s += (double)swsq[i];
        g_ssep[blockIdx.x] = s;
        __threadfence();
        unsigned int t = atomicAdd(&g_done, 1u);
        *sflag = (t == GRID_GEMM - 1) ? 1 : 0;
    }
    __syncthreads();

    /* ---- last CTA computes commit_loss + perplexity ---- */
    if (*sflag) {
        __threadfence();
        __shared__ double wd[8];
        __shared__ float wf[8];
        double sd = g_ssep[tid];
        float s = 0.0f;
        const float invT = 1.0f / (float)T_TOK;
        for (int i = tid; i < KC; i += 256) {
            float e = (float)g_counts[i] * invT;
            s += e * logf(e + 1e-8f);
        }
#pragma unroll
        for (int o = 16; o > 0; o >>= 1) {
            sd += __shfl_down_sync(0xffffffffu, sd, o);
            s  += __shfl_down_sync(0xffffffffu, s, o);
        }
        if (lane == 0) { wd[warp] = sd; wf[warp] = s; }
        __syncthreads();
        if (tid == 0) {
            double td = 0.0; float tf = 0.0f;
#pragma unroll
            for (int i = 0; i < 8; i++) { td += wd[i]; tf += wf[i]; }
            double mse = td / (double)((size_t)T_TOK * DIM);
            out[(size_t)T_TOK * DIM]     = (float)(1.25 * mse);
            out[(size_t)T_TOK * DIM + 1] = expf(-tf);
        }
    }
}

extern "C" void kernel_launch(void* const* d_in, const int* in_sizes, int n_in,
                              void* d_out, int out_size) {
    const float* z   = (const float*)d_in[0];
    const float* emb = (const float*)d_in[1];
    const float* pw  = (const float*)d_in[2];
    const float* pb  = (const float*)d_in[3];
    float* out = (float*)d_out;

    cudaFuncSetAttribute(k_proj, cudaFuncAttributeMaxDynamicSharedMemorySize, SMEM_PROJ);
    cudaFuncSetAttribute(k_gemm, cudaFuncAttributeMaxDynamicSharedMemorySize, SMEM_GEMM);

    k_proj<<<KC / 128, 256, SMEM_PROJ>>>(emb, pw, pb);
    k_gemm<<<GRID_GEMM, 256, SMEM_GEMM>>>(z, out);
}

// round 14
// speedup vs baseline: 1.6001x; 1.6001x over previous
#include <cuda_runtime.h>
#include <cuda_fp16.h>
#include <math.h>
#include <stdint.h>

#define T_TOK 32768
#define DIM   128
#define KC    8192
#define BM    64
#define NT    64
#define ITERS (KC / NT)          /* 128 */
#define THREADS 128
#define GRID_GEMM (T_TOK / BM)   /* 512 */
#define TILE_BYTES 16384
#define SMEM_GEMM (2 * TILE_BYTES)   /* 32KB ring */
#define PAD 132
#define SMEM_PROJ (2 * 128 * PAD * 4)

/* ---------------- device scratch (no allocations) ---------------- */
__device__ __align__(16) unsigned char g_cbt[ITERS * TILE_BYTES]; /* 2MB fp16 B frags */
__device__ float  g_codebook[KC * DIM];
__device__ __align__(16) float g_cnorm[KC];
__device__ int    g_counts[KC];
__device__ double g_ssep[GRID_GEMM];
__device__ unsigned int g_done;

__device__ __forceinline__ uint32_t smem_u32(const void* p) {
    uint32_t a;
    asm("{ .reg .u64 t; cvta.to.shared.u64 t, %1; cvt.u32.u64 %0, t; }"
        : "=r"(a) : "l"(p));
    return a;
}

#define CP16(dst, src) \
    asm volatile("cp.async.cg.shared.global [%0], [%1], 16;" :: "r"((uint32_t)(dst)), "l"(src))
#define CP_COMMIT() asm volatile("cp.async.commit_group;" ::: "memory")
#define CP_WAIT0()  asm volatile("cp.async.wait_group 0;"  ::: "memory")

#define MMA_F16(d, a, b0, b1) \
    asm volatile("mma.sync.aligned.m16n8k16.row.col.f32.f16.f16.f32 " \
                 "{%0,%1,%2,%3}, {%4,%5,%6,%7}, {%8,%9}, {%0,%1,%2,%3};" \
                 : "+f"((d)[0]), "+f"((d)[1]), "+f"((d)[2]), "+f"((d)[3]) \
                 : "r"((a)[0]), "r"((a)[1]), "r"((a)[2]), "r"((a)[3]), \
                   "r"(b0), "r"(b1))

#define INS4(tv0, tv1, tv2, tv3, ti0, ti1, ti2, ti3, v, n) do {               \
    if ((v) < (tv3)) {                                                        \
        if ((v) < (tv2)) {                                                    \
            tv3 = tv2; ti3 = ti2;                                             \
            if ((v) < (tv1)) {                                                \
                tv2 = tv1; ti2 = ti1;                                         \
                if ((v) < (tv0)) { tv1 = tv0; ti1 = ti0; tv0 = (v); ti0 = (n); } \
                else             { tv1 = (v); ti1 = (n); }                    \
            } else { tv2 = (v); ti2 = (n); }                                  \
        } else { tv3 = (v); ti3 = (n); }                                      \
    }                                                                         \
} while (0)

/* ---------------- projection GEMM: C = emb @ W^T + b (128 codes/block) ----------------
   Emits fp32 codebook, cnorm, fp16 packed B fragments; zeroes g_counts and g_done.
   Packed layout per 64-code tile (16KB): [nblk(8)][kblk(8)][lane(32)] x 8B,
   8B = {h(k), h(k+1), h(k+8), h(k+9)}, lane = nl*4 + ksub,
   n = tile*64 + nblk*8 + nl, k = kblk*16 + regsel*8 + ksub*2 + par */
__global__ __launch_bounds__(256, 1)
void k_proj(const float* __restrict__ emb,
            const float* __restrict__ pw,
            const float* __restrict__ pbias) {
    extern __shared__ float ps[];
    float* es = ps;
    float* wsm = ps + 128 * PAD;
    const int tid = threadIdx.x;
    const int tx = tid & 15, ty = tid >> 4;
    const int c0 = blockIdx.x * 128;

    if (tid < 128) g_counts[c0 + tid] = 0;
    if (blockIdx.x == 0 && tid == 0) g_done = 0;

#pragma unroll
    for (int i = 0; i < 16; i++) {
        int f = tid + i * 256;
        int row = f >> 5;
        int c4 = f & 31;
        int sw = (((row >> 2) ^ (c4 & 7)) << 2) | (row & 3);
        float4 v = *((const float4*)(emb + (size_t)(c0 + row) * DIM) + c4);
        es[(4 * c4 + 0) * PAD + sw] = v.x;
        es[(4 * c4 + 1) * PAD + sw] = v.y;
        es[(4 * c4 + 2) * PAD + sw] = v.z;
        es[(4 * c4 + 3) * PAD + sw] = v.w;
        float4 w = *((const float4*)(pw + (size_t)row * DIM) + c4);
        wsm[(4 * c4 + 0) * PAD + sw] = w.x;
        wsm[(4 * c4 + 1) * PAD + sw] = w.y;
        wsm[(4 * c4 + 2) * PAD + sw] = w.z;
        wsm[(4 * c4 + 3) * PAD + sw] = w.w;
    }
    __syncthreads();

    float acc[8][8];
#pragma unroll
    for (int im = 0; im < 8; im++)
#pragma unroll
        for (int jn = 0; jn < 8; jn++) acc[im][jn] = 0.0f;

#pragma unroll 4
    for (int k = 0; k < 128; k++) {
        int s = (k >> 2) & 7;
        const float* er = es + k * PAD;
        const float* wr = wsm + k * PAD;
        float4 a0 = *(const float4*)(er + ((ty ^ s) << 2));
        float4 a1 = *(const float4*)(er + 64 + ((ty ^ s) << 2));
        float4 b0 = *(const float4*)(wr + ((tx ^ s) << 2));
        float4 b1 = *(const float4*)(wr + 64 + ((tx ^ s) << 2));
        float a[8] = {a0.x, a0.y, a0.z, a0.w, a1.x, a1.y, a1.z, a1.w};
        float b[8] = {b0.x, b0.y, b0.z, b0.w, b1.x, b1.y, b1.z, b1.w};
#pragma unroll
        for (int im = 0; im < 8; im++)
#pragma unroll
            for (int jn = 0; jn < 8; jn++)
                acc[im][jn] = fmaf(a[im], b[jn], acc[im][jn]);
    }

    float cnp[8];
#pragma unroll
    for (int im = 0; im < 8; im++) cnp[im] = 0.0f;

#pragma unroll
    for (int im = 0; im < 8; im++) {
        int cl = (im < 4) ? (ty * 4 + im) : (64 + ty * 4 + im - 4);
        int cg = c0 + cl;
        int tile = cg >> 6, nblk = (cg >> 3) & 7, nl = cg & 7;
#pragma unroll
        for (int jn = 0; jn < 8; jn++) {
            int d = (jn < 4) ? (tx * 4 + jn) : (64 + tx * 4 + jn - 4);
            float val = acc[im][jn] + pbias[d];
            g_codebook[(size_t)cg * DIM + d] = val;
            cnp[im] = fmaf(val, val, cnp[im]);
            int kblk = d >> 4, kin = d & 15;
            int regsel = kin >> 3, ksub = (kin & 7) >> 1, par = kin & 1;
            int lane = nl * 4 + ksub;
            size_t off = (size_t)tile * TILE_BYTES + nblk * 2048 + kblk * 256
                       + lane * 8 + regsel * 4 + par * 2;
            *(__half*)(g_cbt + off) = __float2half_rn(val);
        }
    }
#pragma unroll
    for (int im = 0; im < 8; im++) {
#pragma unroll
        for (int o = 8; o > 0; o >>= 1)
            cnp[im] += __shfl_xor_sync(0xffffffffu, cnp[im], o, 16);
    }
    if (tx == 0) {
#pragma unroll
        for (int im = 0; im < 8; im++) {
            int cl = (im < 4) ? (ty * 4 + im) : (64 + ty * 4 + im - 4);
            g_cnorm[c0 + cl] = cnp[im];
        }
    }
}

/* ---------------- fused: fp16 HMMA GEMM + top-4 + exact rescore + loss ----------------
   128-thread CTAs (BM=64): 4 CTAs/SM run async -> cross-CTA latency overlap. */
__global__ __launch_bounds__(THREADS, 4)
void k_gemm(const float* __restrict__ z, float* __restrict__ out) {
    extern __shared__ unsigned char smem[];
    const uint32_t sb = smem_u32(smem);
    const int tid = threadIdx.x;
    const int lane = tid & 31;
    const int warp = tid >> 5;          /* 0..3 */
    const int r = lane >> 2;
    const int cc = lane & 3;
    const int m0 = blockIdx.x * BM;

    /* prologue: prefetch B tile 0 (16KB: 8 x CP16 per thread) */
#pragma unroll
    for (int j = 0; j < 8; j++) {
        uint32_t off = (uint32_t)(tid + j * THREADS) * 16;
        CP16(sb + off, g_cbt + off);
    }
    CP_COMMIT();

    /* A fragments (fp16) in registers: warp owns rows m0 + warp*16 .. +15 */
    uint32_t A[8][4];
    {
        const float* z0 = z + (size_t)(m0 + warp * 16 + r) * DIM;
#pragma unroll
        for (int kb = 0; kb < 8; kb++) {
#pragma unroll
            for (int q = 0; q < 4; q++) {
                const float* src = z0 + ((q & 1) ? 8 * DIM : 0) + kb * 16 + (q >> 1) * 8 + cc * 2;
                float2 v = *(const float2*)src;
                __half2 hh = __floats2half2_rn(v.x, v.y);
                A[kb][q] = *(uint32_t*)&hh;
            }
        }
    }

    float av0 = 3.4e38f, av1 = 3.4e38f, av2 = 3.4e38f, av3 = 3.4e38f;
    float bv0 = 3.4e38f, bv1 = 3.4e38f, bv2 = 3.4e38f, bv3 = 3.4e38f;
    int ai0 = 0, ai1 = 0, ai2 = 0, ai3 = 0;
    int bi0 = 0, bi1 = 0, bi2 = 0, bi3 = 0;

    for (int i = 0; i < ITERS; i++) {
        CP_WAIT0();
        __syncthreads();
        if (i + 1 < ITERS) {
            const unsigned char* src = g_cbt + (size_t)(i + 1) * TILE_BYTES;
            uint32_t dst = sb + ((i + 1) & 1) * TILE_BYTES;
#pragma unroll
            for (int j = 0; j < 8; j++) {
                uint32_t off = (uint32_t)(tid + j * THREADS) * 16;
                CP16(dst + off, src + off);
            }
            CP_COMMIT();
        }

        float acc[8][4];
#pragma unroll
        for (int nb = 0; nb < 8; nb++)
#pragma unroll
            for (int q = 0; q < 4; q++) acc[nb][q] = 0.0f;

        const uint32_t bbase = sb + (i & 1) * TILE_BYTES + lane * 8;
#pragma unroll
        for (int kb = 0; kb < 8; kb++) {
#pragma unroll
            for (int nb = 0; nb < 8; nb++) {
                uint32_t b0, b1;
                asm volatile("ld.shared.v2.b32 {%0,%1},[%2];"
                             : "=r"(b0), "=r"(b1) : "r"(bbase + nb * 2048 + kb * 256));
                MMA_F16(acc[nb], A[kb], b0, b1);
            }
        }

        const int n0i = i * 64;
#pragma unroll
        for (int nb = 0; nb < 8; nb++) {
            int n = n0i + nb * 8 + cc * 2;
            float2 cn = __ldg((const float2*)(g_cnorm + n));
            float s0 = fmaf(-2.0f, acc[nb][0], cn.x);
            float s1 = fmaf(-2.0f, acc[nb][1], cn.y);
            float s2 = fmaf(-2.0f, acc[nb][2], cn.x);
            float s3 = fmaf(-2.0f, acc[nb][3], cn.y);
            INS4(av0, av1, av2, av3, ai0, ai1, ai2, ai3, s0, n);
            INS4(av0, av1, av2, av3, ai0, ai1, ai2, ai3, s1, n + 1);
            INS4(bv0, bv1, bv2, bv3, bi0, bi1, bi2, bi3, s2, n);
            INS4(bv0, bv1, bv2, bv3, bi0, bi1, bi2, bi3, s3, n + 1);
        }
    }

    /* merge top-4 across the 4 cc lanes */
#pragma unroll
    for (int off = 1; off <= 2; off <<= 1) {
        float wa0 = __shfl_xor_sync(0xffffffffu, av0, off);
        float wa1 = __shfl_xor_sync(0xffffffffu, av1, off);
        float wa2 = __shfl_xor_sync(0xffffffffu, av2, off);
        float wa3 = __shfl_xor_sync(0xffffffffu, av3, off);
        int ja0 = __shfl_xor_sync(0xffffffffu, ai0, off);
        int ja1 = __shfl_xor_sync(0xffffffffu, ai1, off);
        int ja2 = __shfl_xor_sync(0xffffffffu, ai2, off);
        int ja3 = __shfl_xor_sync(0xffffffffu, ai3, off);
        float wb0 = __shfl_xor_sync(0xffffffffu, bv0, off);
        float wb1 = __shfl_xor_sync(0xffffffffu, bv1, off);
        float wb2 = __shfl_xor_sync(0xffffffffu, bv2, off);
        float wb3 = __shfl_xor_sync(0xffffffffu, bv3, off);
        int jb0 = __shfl_xor_sync(0xffffffffu, bi0, off);
        int jb1 = __shfl_xor_sync(0xffffffffu, bi1, off);
        int jb2 = __shfl_xor_sync(0xffffffffu, bi2, off);
        int jb3 = __shfl_xor_sync(0xffffffffu, bi3, off);
        INS4(av0, av1, av2, av3, ai0, ai1, ai2, ai3, wa0, ja0);
        INS4(av0, av1, av2, av3, ai0, ai1, ai2, ai3, wa1, ja1);
        INS4(av0, av1, av2, av3, ai0, ai1, ai2, ai3, wa2, ja2);
        INS4(av0, av1, av2, av3, ai0, ai1, ai2, ai3, wa3, ja3);
        INS4(bv0, bv1, bv2, bv3, bi0, bi1, bi2, bi3, wb0, jb0);
        INS4(bv0, bv1, bv2, bv3, bi0, bi1, bi2, bi3, wb1, jb1);
        INS4(bv0, bv1, bv2, bv3, bi0, bi1, bi2, bi3, wb2, jb2);
        INS4(bv0, bv1, bv2, bv3, bi0, bi1, bi2, bi3, wb3, jb3);
    }

    /* ---- fused rescore: stash candidates in smem (ring drained) ---- */
    CP_WAIT0();
    __syncthreads();
    int4*  scand = (int4*)smem;                 /* 64 x 16B = 1KB */
    float* swsq  = (float*)(smem + 1024);
    int*   sflag = (int*)(smem + 1024 + 16);
    if (cc == 0) {
        scand[warp * 16 + r]     = make_int4(ai0, ai1, ai2, ai3);
        scand[warp * 16 + r + 8] = make_int4(bi0, bi1, bi2, bi3);
    }
    __syncthreads();

    float warp_sq = 0.0f;
    for (int j = 0; j < 16; j++) {
        const int tl = warp * 16 + j;
        const int t = m0 + tl;
        int4 cd = scand[tl];
        float4 zv = ((const float4*)(z + (size_t)t * DIM))[lane];
        float4 c0 = ((const float4*)(g_codebook + (size_t)cd.x * DIM))[lane];
        float4 c1 = ((const float4*)(g_codebook + (size_t)cd.y * DIM))[lane];
        float4 c2 = ((const float4*)(g_codebook + (size_t)cd.z * DIM))[lane];
        float4 c3 = ((const float4*)(g_codebook + (size_t)cd.w * DIM))[lane];
        float d0 = zv.x * c0.x + zv.y * c0.y + zv.z * c0.z + zv.w * c0.w;
        float d1 = zv.x * c1.x + zv.y * c1.y + zv.z * c1.z + zv.w * c1.w;
        float d2 = zv.x * c2.x + zv.y * c2.y + zv.z * c2.z + zv.w * c2.w;
        float d3 = zv.x * c3.x + zv.y * c3.y + zv.z * c3.z + zv.w * c3.w;
#pragma unroll
        for (int o = 16; o > 0; o >>= 1) {
            d0 += __shfl_xor_sync(0xffffffffu, d0, o);
            d1 += __shfl_xor_sync(0xffffffffu, d1, o);
            d2 += __shfl_xor_sync(0xffffffffu, d2, o);
            d3 += __shfl_xor_sync(0xffffffffu, d3, o);
        }
        float s0 = g_cnorm[cd.x] - 2.0f * d0;
        float s1 = g_cnorm[cd.y] - 2.0f * d1;
        float s2 = g_cnorm[cd.z] - 2.0f * d2;
        float s3 = g_cnorm[cd.w] - 2.0f * d3;

        float bs = s0; int bi = cd.x; float4 c = c0;
        if (s1 < bs || (s1 == bs && cd.y < bi)) { bs = s1; bi = cd.y; c = c1; }
        if (s2 < bs || (s2 == bs && cd.z < bi)) { bs = s2; bi = cd.z; c = c2; }
        if (s3 < bs || (s3 == bs && cd.w < bi)) { bs = s3; bi = cd.w; c = c3; }

        float dx = c.x - zv.x, dy = c.y - zv.y, dz = c.z - zv.z, dw = c.w - zv.w;
        float4 o4;
        o4.x = zv.x + dx; o4.y = zv.y + dy; o4.z = zv.z + dz; o4.w = zv.w + dw;
        ((float4*)(out + (size_t)t * DIM))[lane] = o4;

        float sq = dx * dx + dy * dy + dz * dz + dw * dw;
#pragma unroll
        for (int o = 16; o > 0; o >>= 1) sq += __shfl_xor_sync(0xffffffffu, sq, o);
        warp_sq += sq;
        if (lane == 0) atomicAdd(&g_counts[bi], 1);
    }
    if (lane == 0) swsq[warp] = warp_sq;
    __syncthreads();
    if (tid == 0) {
        double s = 0.0;
#pragma unroll
        for (int i = 0; i < 4; i++) s += (double)swsq[i];
        g_ssep[blockIdx.x] = s;
        __threadfence();
        unsigned int t = atomicAdd(&g_done, 1u);
        *sflag = (t == GRID_GEMM - 1) ? 1 : 0;
    }
    __syncthreads();

    /* ---- last CTA computes commit_loss + perplexity ---- */
    if (*sflag) {
        __threadfence();
        __shared__ double wd[4];
        __shared__ float wf[4];
        double sd = g_ssep[tid] + g_ssep[tid + 128] + g_ssep[tid + 256] + g_ssep[tid + 384];
        float s = 0.0f;
        const float invT = 1.0f / (float)T_TOK;
        for (int i = tid; i < KC; i += THREADS) {
            float e = (float)g_counts[i] * invT;
            s += e * logf(e + 1e-8f);
        }
#pragma unroll
        for (int o = 16; o > 0; o >>= 1) {
            sd += __shfl_down_sync(0xffffffffu, sd, o);
            s  += __shfl_down_sync(0xffffffffu, s, o);
        }
        if (lane == 0) { wd[warp] = sd; wf[warp] = s; }
        __syncthreads();
        if (tid == 0) {
            double td = 0.0; float tf = 0.0f;
#pragma unroll
            for (int i = 0; i < 4; i++) { td += wd[i]; tf += wf[i]; }
            double mse = td / (double)((size_t)T_TOK * DIM);
            out[(size_t)T_TOK * DIM]     = (float)(1.25 * mse);
            out[(size_t)T_TOK * DIM + 1] = expf(-tf);
        }
    }
}

extern "C" void kernel_launch(void* const* d_in, const int* in_sizes, int n_in,
                              void* d_out, int out_size) {
    const float* z   = (const float*)d_in[0];
    const float* emb = (const float*)d_in[1];
    const float* pw  = (const float*)d_in[2];
    const float* pb  = (const float*)d_in[3];
    float* out = (float*)d_out;

    cudaFuncSetAttribute(k_proj, cudaFuncAttributeMaxDynamicSharedMemorySize, SMEM_PROJ);
    cudaFuncSetAttribute(k_gemm, cudaFuncAttributeMaxDynamicSharedMemorySize, SMEM_GEMM);
    cudaFuncSetAttribute(k_gemm, cudaFuncAttributePreferredSharedMemoryCarveout, 100);

    k_proj<<<KC / 128, 256, SMEM_PROJ>>>(emb, pw, pb);
    k_gemm<<<GRID_GEMM, THREADS, SMEM_GEMM>>>(z, out);
}

// round 15
// speedup vs baseline: 1.7968x; 1.1229x over previous
#include <cuda_runtime.h>
#include <cuda_fp16.h>
#include <math.h>
#include <stdint.h>

#define T_TOK 32768
#define DIM   128
#define KC    8192
#define BM    128
#define NT    64
#define ITERS (KC / NT)          /* 128 */
#define GRID_GEMM (T_TOK / BM)   /* 256 */
#define TILE_BYTES 16384
#define SMEM_GEMM (3 * TILE_BYTES)   /* 48KB: 3-deep ring */
#define PAD 132
#define SMEM_PROJ (2 * 128 * PAD * 4)

/* ---------------- device scratch (no allocations) ---------------- */
__device__ __align__(16) unsigned char g_cbt[ITERS * TILE_BYTES]; /* 2MB fp16 B frags */
__device__ float  g_codebook[KC * DIM];
__device__ __align__(16) float g_cnorm[KC];
__device__ int    g_counts[KC];
__device__ double g_ssep[GRID_GEMM];
__device__ unsigned int g_done;

__device__ __forceinline__ uint32_t smem_u32(const void* p) {
    uint32_t a;
    asm("{ .reg .u64 t; cvta.to.shared.u64 t, %1; cvt.u32.u64 %0, t; }"
        : "=r"(a) : "l"(p));
    return a;
}

#define CP16(dst, src) \
    asm volatile("cp.async.cg.shared.global [%0], [%1], 16;" :: "r"((uint32_t)(dst)), "l"(src))
#define CP_COMMIT() asm volatile("cp.async.commit_group;" ::: "memory")
#define CP_WAIT1()  asm volatile("cp.async.wait_group 1;"  ::: "memory")
#define CP_WAIT0()  asm volatile("cp.async.wait_group 0;"  ::: "memory")

#define MMA_F16(d, a, b0, b1) \
    asm volatile("mma.sync.aligned.m16n8k16.row.col.f32.f16.f16.f32 " \
                 "{%0,%1,%2,%3}, {%4,%5,%6,%7}, {%8,%9}, {%0,%1,%2,%3};" \
                 : "+f"((d)[0]), "+f"((d)[1]), "+f"((d)[2]), "+f"((d)[3]) \
                 : "r"((a)[0]), "r"((a)[1]), "r"((a)[2]), "r"((a)[3]), \
                   "r"(b0), "r"(b1))

#define INS4(tv0, tv1, tv2, tv3, ti0, ti1, ti2, ti3, v, n) do {               \
    if ((v) < (tv3)) {                                                        \
        if ((v) < (tv2)) {                                                    \
            tv3 = tv2; ti3 = ti2;                                             \
            if ((v) < (tv1)) {                                                \
                tv2 = tv1; ti2 = ti1;                                         \
                if ((v) < (tv0)) { tv1 = tv0; ti1 = ti0; tv0 = (v); ti0 = (n); } \
                else             { tv1 = (v); ti1 = (n); }                    \
            } else { tv2 = (v); ti2 = (n); }                                  \
        } else { tv3 = (v); ti3 = (n); }                                      \
    }                                                                         \
} while (0)

/* ---------------- projection GEMM: C = emb @ W^T + b (128 codes/block) ----------------
   Emits fp32 codebook, cnorm, fp16 packed B fragments; zeroes g_counts and g_done.
   Packed layout per 64-code tile (16KB): [nbpair(4)][kblk(8)][lane(32)] x 16B,
   16B = {frag(nb=2p) 8B, frag(nb=2p+1) 8B}; 8B = {h(k), h(k+1), h(k+8), h(k+9)},
   lane = nl*4 + ksub; n = tile*64 + nblk*8 + nl, k = kblk*16 + regsel*8 + ksub*2 + par */
__global__ __launch_bounds__(256, 1)
void k_proj(const float* __restrict__ emb,
            const float* __restrict__ pw,
            const float* __restrict__ pbias) {
    extern __shared__ float ps[];
    float* es = ps;
    float* wsm = ps + 128 * PAD;
    const int tid = threadIdx.x;
    const int tx = tid & 15, ty = tid >> 4;
    const int c0 = blockIdx.x * 128;

    if (tid < 128) g_counts[c0 + tid] = 0;
    if (blockIdx.x == 0 && tid == 0) g_done = 0;

#pragma unroll
    for (int i = 0; i < 16; i++) {
        int f = tid + i * 256;
        int row = f >> 5;
        int c4 = f & 31;
        int sw = (((row >> 2) ^ (c4 & 7)) << 2) | (row & 3);
        float4 v = *((const float4*)(emb + (size_t)(c0 + row) * DIM) + c4);
        es[(4 * c4 + 0) * PAD + sw] = v.x;
        es[(4 * c4 + 1) * PAD + sw] = v.y;
        es[(4 * c4 + 2) * PAD + sw] = v.z;
        es[(4 * c4 + 3) * PAD + sw] = v.w;
        float4 w = *((const float4*)(pw + (size_t)row * DIM) + c4);
        wsm[(4 * c4 + 0) * PAD + sw] = w.x;
        wsm[(4 * c4 + 1) * PAD + sw] = w.y;
        wsm[(4 * c4 + 2) * PAD + sw] = w.z;
        wsm[(4 * c4 + 3) * PAD + sw] = w.w;
    }
    __syncthreads();

    float acc[8][8];
#pragma unroll
    for (int im = 0; im < 8; im++)
#pragma unroll
        for (int jn = 0; jn < 8; jn++) acc[im][jn] = 0.0f;

#pragma unroll 4
    for (int k = 0; k < 128; k++) {
        int s = (k >> 2) & 7;
        const float* er = es + k * PAD;
        const float* wr = wsm + k * PAD;
        float4 a0 = *(const float4*)(er + ((ty ^ s) << 2));
        float4 a1 = *(const float4*)(er + 64 + ((ty ^ s) << 2));
        float4 b0 = *(const float4*)(wr + ((tx ^ s) << 2));
        float4 b1 = *(const float4*)(wr + 64 + ((tx ^ s) << 2));
        float a[8] = {a0.x, a0.y, a0.z, a0.w, a1.x, a1.y, a1.z, a1.w};
        float b[8] = {b0.x, b0.y, b0.z, b0.w, b1.x, b1.y, b1.z, b1.w};
#pragma unroll
        for (int im = 0; im < 8; im++)
#pragma unroll
            for (int jn = 0; jn < 8; jn++)
                acc[im][jn] = fmaf(a[im], b[jn], acc[im][jn]);
    }

    float cnp[8];
#pragma unroll
    for (int im = 0; im < 8; im++) cnp[im] = 0.0f;

#pragma unroll
    for (int im = 0; im < 8; im++) {
        int cl = (im < 4) ? (ty * 4 + im) : (64 + ty * 4 + im - 4);
        int cg = c0 + cl;
        int tile = cg >> 6, nblk = (cg >> 3) & 7, nl = cg & 7;
        int nbpair = nblk >> 1, nbw = nblk & 1;
#pragma unroll
        for (int jn = 0; jn < 8; jn++) {
            int d = (jn < 4) ? (tx * 4 + jn) : (64 + tx * 4 + jn - 4);
            float val = acc[im][jn] + pbias[d];
            g_codebook[(size_t)cg * DIM + d] = val;
            cnp[im] = fmaf(val, val, cnp[im]);
            int kblk = d >> 4, kin = d & 15;
            int regsel = kin >> 3, ksub = (kin & 7) >> 1, par = kin & 1;
            int lane = nl * 4 + ksub;
            size_t off = (size_t)tile * TILE_BYTES + nbpair * 4096 + kblk * 512
                       + lane * 16 + nbw * 8 + regsel * 4 + par * 2;
            *(__half*)(g_cbt + off) = __float2half_rn(val);
        }
    }
#pragma unroll
    for (int im = 0; im < 8; im++) {
#pragma unroll
        for (int o = 8; o > 0; o >>= 1)
            cnp[im] += __shfl_xor_sync(0xffffffffu, cnp[im], o, 16);
    }
    if (tx == 0) {
#pragma unroll
        for (int im = 0; im < 8; im++) {
            int cl = (im < 4) ? (ty * 4 + im) : (64 + ty * 4 + im - 4);
            g_cnorm[c0 + cl] = cnp[im];
        }
    }
}

/* ---------------- fused: fp16 HMMA GEMM + top-4 + exact rescore + loss ----------------
   v4 B loads: one LDS.128 feeds two MMAs (nb pair). 3-deep ring as R10/R11. */
__global__ __launch_bounds__(256, 2)
void k_gemm(const float* __restrict__ z, float* __restrict__ out) {
    extern __shared__ unsigned char smem[];
    const uint32_t sb = smem_u32(smem);
    const int tid = threadIdx.x;
    const int lane = tid & 31;
    const int warp = tid >> 5;
    const int r = lane >> 2;
    const int cc = lane & 3;
    const int m0 = blockIdx.x * BM;

    /* prologue: prefetch B tiles 0 and 1 into ring slots 0,1 */
#pragma unroll
    for (int t = 0; t < 2; t++) {
        const unsigned char* src = g_cbt + (size_t)t * TILE_BYTES;
        uint32_t dst = sb + t * TILE_BYTES;
#pragma unroll
        for (int j = 0; j < 4; j++) {
            uint32_t off = (uint32_t)(tid + j * 256) * 16;
            CP16(dst + off, src + off);
        }
        CP_COMMIT();
    }

    /* A fragments (fp16) in registers */
    uint32_t A[8][4];
    {
        const float* z0 = z + (size_t)(m0 + warp * 16 + r) * DIM;
#pragma unroll
        for (int kb = 0; kb < 8; kb++) {
#pragma unroll
            for (int q = 0; q < 4; q++) {
                const float* src = z0 + ((q & 1) ? 8 * DIM : 0) + kb * 16 + (q >> 1) * 8 + cc * 2;
                float2 v = *(const float2*)src;
                __half2 hh = __floats2half2_rn(v.x, v.y);
                A[kb][q] = *(uint32_t*)&hh;
            }
        }
    }

    float av0 = 3.4e38f, av1 = 3.4e38f, av2 = 3.4e38f, av3 = 3.4e38f;
    float bv0 = 3.4e38f, bv1 = 3.4e38f, bv2 = 3.4e38f, bv3 = 3.4e38f;
    int ai0 = 0, ai1 = 0, ai2 = 0, ai3 = 0;
    int bi0 = 0, bi1 = 0, bi2 = 0, bi3 = 0;

    int buf = 0, nbuf = 2;
    for (int i = 0; i < ITERS; i++) {
        CP_WAIT1();
        __syncthreads();
        if (i + 2 < ITERS) {
            const unsigned char* src = g_cbt + (size_t)(i + 2) * TILE_BYTES;
            uint32_t dst = sb + nbuf * TILE_BYTES;
#pragma unroll
            for (int j = 0; j < 4; j++) {
                uint32_t off = (uint32_t)(tid + j * 256) * 16;
                CP16(dst + off, src + off);
            }
        }
        CP_COMMIT();

        float acc[8][4];
#pragma unroll
        for (int nb = 0; nb < 8; nb++)
#pragma unroll
            for (int q = 0; q < 4; q++) acc[nb][q] = 0.0f;

        const uint32_t bbase = sb + buf * TILE_BYTES + lane * 16;
#pragma unroll
        for (int kb = 0; kb < 8; kb++) {
#pragma unroll
            for (int p = 0; p < 4; p++) {
                uint32_t b0, b1, b2, b3;
                asm volatile("ld.shared.v4.b32 {%0,%1,%2,%3},[%4];"
                             : "=r"(b0), "=r"(b1), "=r"(b2), "=r"(b3)
                             : "r"(bbase + p * 4096 + kb * 512));
                MMA_F16(acc[2 * p],     A[kb], b0, b1);
                MMA_F16(acc[2 * p + 1], A[kb], b2, b3);
            }
        }

        const int n0i = i * 64;
#pragma unroll
        for (int nb = 0; nb < 8; nb++) {
            int n = n0i + nb * 8 + cc * 2;
            float2 cn = __ldg((const float2*)(g_cnorm + n));
            float s0 = fmaf(-2.0f, acc[nb][0], cn.x);
            float s1 = fmaf(-2.0f, acc[nb][1], cn.y);
            float s2 = fmaf(-2.0f, acc[nb][2], cn.x);
            float s3 = fmaf(-2.0f, acc[nb][3], cn.y);
            INS4(av0, av1, av2, av3, ai0, ai1, ai2, ai3, s0, n);
            INS4(av0, av1, av2, av3, ai0, ai1, ai2, ai3, s1, n + 1);
            INS4(bv0, bv1, bv2, bv3, bi0, bi1, bi2, bi3, s2, n);
            INS4(bv0, bv1, bv2, bv3, bi0, bi1, bi2, bi3, s3, n + 1);
        }
        buf = (buf == 2) ? 0 : buf + 1;
        nbuf = (nbuf == 2) ? 0 : nbuf + 1;
    }

    /* merge top-4 across the 4 cc lanes */
#pragma unroll
    for (int off = 1; off <= 2; off <<= 1) {
        float wa0 = __shfl_xor_sync(0xffffffffu, av0, off);
        float wa1 = __shfl_xor_sync(0xffffffffu, av1, off);
        float wa2 = __shfl_xor_sync(0xffffffffu, av2, off);
        float wa3 = __shfl_xor_sync(0xffffffffu, av3, off);
        int ja0 = __shfl_xor_sync(0xffffffffu, ai0, off);
        int ja1 = __shfl_xor_sync(0xffffffffu, ai1, off);
        int ja2 = __shfl_xor_sync(0xffffffffu, ai2, off);
        int ja3 = __shfl_xor_sync(0xffffffffu, ai3, off);
        float wb0 = __shfl_xor_sync(0xffffffffu, bv0, off);
        float wb1 = __shfl_xor_sync(0xffffffffu, bv1, off);
        float wb2 = __shfl_xor_sync(0xffffffffu, bv2, off);
        float wb3 = __shfl_xor_sync(0xffffffffu, bv3, off);
        int jb0 = __shfl_xor_sync(0xffffffffu, bi0, off);
        int jb1 = __shfl_xor_sync(0xffffffffu, bi1, off);
        int jb2 = __shfl_xor_sync(0xffffffffu, bi2, off);
        int jb3 = __shfl_xor_sync(0xffffffffu, bi3, off);
        INS4(av0, av1, av2, av3, ai0, ai1, ai2, ai3, wa0, ja0);
        INS4(av0, av1, av2, av3, ai0, ai1, ai2, ai3, wa1, ja1);
        INS4(av0, av1, av2, av3, ai0, ai1, ai2, ai3, wa2, ja2);
        INS4(av0, av1, av2, av3, ai0, ai1, ai2, ai3, wa3, ja3);
        INS4(bv0, bv1, bv2, bv3, bi0, bi1, bi2, bi3, wb0, jb0);
        INS4(bv0, bv1, bv2, bv3, bi0, bi1, bi2, bi3, wb1, jb1);
        INS4(bv0, bv1, bv2, bv3, bi0, bi1, bi2, bi3, wb2, jb2);
        INS4(bv0, bv1, bv2, bv3, bi0, bi1, bi2, bi3, wb3, jb3);
    }

    /* ---- fused rescore: stash candidates in smem (ring drained) ---- */
    CP_WAIT0();
    __syncthreads();
    int4*  scand = (int4*)smem;
    float* swsq  = (float*)(smem + 2048);
    int*   sflag = (int*)(smem + 2048 + 32);
    if (cc == 0) {
        scand[warp * 16 + r]     = make_int4(ai0, ai1, ai2, ai3);
        scand[warp * 16 + r + 8] = make_int4(bi0, bi1, bi2, bi3);
    }
    __syncthreads();

    float warp_sq = 0.0f;
    for (int j = 0; j < 16; j++) {
        const int tl = warp * 16 + j;
        const int t = m0 + tl;
        int4 cd = scand[tl];
        float4 zv = ((const float4*)(z + (size_t)t * DIM))[lane];
        float4 c0 = ((const float4*)(g_codebook + (size_t)cd.x * DIM))[lane];
        float4 c1 = ((const float4*)(g_codebook + (size_t)cd.y * DIM))[lane];
        float4 c2 = ((const float4*)(g_codebook + (size_t)cd.z * DIM))[lane];
        float4 c3 = ((const float4*)(g_codebook + (size_t)cd.w * DIM))[lane];
        float d0 = zv.x * c0.x + zv.y * c0.y + zv.z * c0.z + zv.w * c0.w;
        float d1 = zv.x * c1.x + zv.y * c1.y + zv.z * c1.z + zv.w * c1.w;
        float d2 = zv.x * c2.x + zv.y * c2.y + zv.z * c2.z + zv.w * c2.w;
        float d3 = zv.x * c3.x + zv.y * c3.y + zv.z * c3.z + zv.w * c3.w;
#pragma unroll
        for (int o = 16; o > 0; o >>= 1) {
            d0 += __shfl_xor_sync(0xffffffffu, d0, o);
            d1 += __shfl_xor_sync(0xffffffffu, d1, o);
            d2 += __shfl_xor_sync(0xffffffffu, d2, o);
            d3 += __shfl_xor_sync(0xffffffffu, d3, o);
        }
        float s0 = g_cnorm[cd.x] - 2.0f * d0;
        float s1 = g_cnorm[cd.y] - 2.0f * d1;
        float s2 = g_cnorm[cd.z] - 2.0f * d2;
        float s3 = g_cnorm[cd.w] - 2.0f * d3;

        float bs = s0; int bi = cd.x; float4 c = c0;
        if (s1 < bs || (s1 == bs && cd.y < bi)) { bs = s1; bi = cd.y; c = c1; }
        if (s2 < bs || (s2 == bs && cd.z < bi)) { bs = s2; bi = cd.z; c = c2; }
        if (s3 < bs || (s3 == bs && cd.w < bi)) { bs = s3; bi = cd.w; c = c3; }

        float dx = c.x - zv.x, dy = c.y - zv.y, dz = c.z - zv.z, dw = c.w - zv.w;
        float4 o4;
        o4.x = zv.x + dx; o4.y = zv.y + dy; o4.z = zv.z + dz; o4.w = zv.w + dw;
        ((float4*)(out + (size_t)t * DIM))[lane] = o4;

        float sq = dx * dx + dy * dy + dz * dz + dw * dw;
#pragma unroll
        for (int o = 16; o > 0; o >>= 1) sq += __shfl_xor_sync(0xffffffffu, sq, o);
        warp_sq += sq;
        if (lane == 0) atomicAdd(&g_counts[bi], 1);
    }
    if (lane == 0) swsq[warp] = warp_sq;
    __syncthreads();
    if (tid == 0) {
        double s = 0.0;
#pragma unroll
        for (int i = 0; i < 8; i++) s += (double)swsq[i];
        g_ssep[blockIdx.x] = s;
        __threadfence();
        unsigned int t = atomicAdd(&g_done, 1u);
        *sflag = (t == GRID_GEMM - 1) ? 1 : 0;
    }
    __syncthreads();

    /* ---- last CTA computes commit_loss + perplexity ---- */
    if (*sflag) {
        __threadfence();
        __shared__ double wd[8];
        __shared__ float wf[8];
        double sd = g_ssep[tid];
        float s = 0.0f;
        const float invT = 1.0f / (float)T_TOK;
        for (int i = tid; i < KC; i += 256) {
            float e = (float)g_counts[i] * invT;
            s += e * logf(e + 1e-8f);
        }
#pragma unroll
        for (int o = 16; o > 0; o >>= 1) {
            sd += __shfl_down_sync(0xffffffffu, sd, o);
            s  += __shfl_down_sync(0xffffffffu, s, o);
        }
        if (lane == 0) { wd[warp] = sd; wf[warp] = s; }
        __syncthreads();
        if (tid == 0) {
            double td = 0.0; float tf = 0.0f;
#pragma unroll
            for (int i = 0; i < 8; i++) { td += wd[i]; tf += wf[i]; }
            double mse = td / (double)((size_t)T_TOK * DIM);
            out[(size_t)T_TOK * DIM]     = (float)(1.25 * mse);
            out[(size_t)T_TOK * DIM + 1] = expf(-tf);
        }
    }
}

extern "C" void kernel_launch(void* const* d_in, const int* in_sizes, int n_in,
                              void* d_out, int out_size) {
    const float* z   = (const float*)d_in[0];
    const float* emb = (const float*)d_in[1];
    const float* pw  = (const float*)d_in[2];
    const float* pb  = (const float*)d_in[3];
    float* out = (float*)d_out;

    cudaFuncSetAttribute(k_proj, cudaFuncAttributeMaxDynamicSharedMemorySize, SMEM_PROJ);
    cudaFuncSetAttribute(k_gemm, cudaFuncAttributeMaxDynamicSharedMemorySize, SMEM_GEMM);

    k_proj<<<KC / 128, 256, SMEM_PROJ>>>(emb, pw, pb);
    k_gemm<<<GRID_GEMM, 256, SMEM_GEMM>>>(z, out);
}

// round 16
// speedup vs baseline: 2.1482x; 1.1956x over previous
#include <cuda_runtime.h>
#include <cuda_fp16.h>
#include <math.h>
#include <stdint.h>

#define T_TOK 32768
#define DIM   128
#define KC    8192
#define BM    128
#define NT    64
#define ITERS (KC / NT)          /* 128 */
#define GRID_GEMM (T_TOK / BM)   /* 256 */
#define TILE_BYTES 16384
#define SMEM_GEMM (3 * TILE_BYTES)   /* 48KB: 3-deep ring */
#define PAD 132
#define SMEM_PROJ (2 * 128 * PAD * 4)

/* ---------------- device scratch (no allocations) ---------------- */
__device__ __align__(16) unsigned char g_cbt[ITERS * TILE_BYTES]; /* 2MB fp16 B frags */
__device__ float  g_codebook[KC * DIM];
__device__ __align__(16) float g_cnorm[KC];
__device__ int    g_counts[KC];
__device__ double g_ssep[GRID_GEMM];
__device__ unsigned int g_done;

__device__ __forceinline__ uint32_t smem_u32(const void* p) {
    uint32_t a;
    asm("{ .reg .u64 t; cvta.to.shared.u64 t, %1; cvt.u32.u64 %0, t; }"
        : "=r"(a) : "l"(p));
    return a;
}

#define CP16(dst, src) \
    asm volatile("cp.async.cg.shared.global [%0], [%1], 16;" :: "r"((uint32_t)(dst)), "l"(src))
#define CP_COMMIT() asm volatile("cp.async.commit_group;" ::: "memory")
#define CP_WAIT1()  asm volatile("cp.async.wait_group 1;"  ::: "memory")
#define CP_WAIT0()  asm volatile("cp.async.wait_group 0;"  ::: "memory")

/* fp16-accumulator HMMA: D,C are 2 x f16x2 regs */
#define MMA_F16ACC(d, a, b0, b1) \
    asm volatile("mma.sync.aligned.m16n8k16.row.col.f16.f16.f16.f16 " \
                 "{%0,%1}, {%2,%3,%4,%5}, {%6,%7}, {%0,%1};" \
                 : "+r"((d)[0]), "+r"((d)[1]) \
                 : "r"((a)[0]), "r"((a)[1]), "r"((a)[2]), "r"((a)[3]), \
                   "r"(b0), "r"(b1))

#define INS2(tv0, tv1, ti0, ti1, v, n) do {                                   \
    if ((v) < (tv1)) {                                                        \
        if ((v) < (tv0)) { tv1 = tv0; ti1 = ti0; tv0 = (v); ti0 = (n); }      \
        else             { tv1 = (v); ti1 = (n); }                            \
    }                                                                         \
} while (0)

/* ---------------- projection GEMM: C = emb @ W^T + b (128 codes/block) ----------------
   Emits fp32 codebook, cnorm, fp16 packed B fragments; zeroes g_counts and g_done.
   Packed layout per 64-code tile (16KB): [nblk(8)][kblk(8)][lane(32)] x 8B,
   8B = {h(k), h(k+1), h(k+8), h(k+9)}, lane = nl*4 + ksub,
   n = tile*64 + nblk*8 + nl, k = kblk*16 + regsel*8 + ksub*2 + par */
__global__ __launch_bounds__(256, 1)
void k_proj(const float* __restrict__ emb,
            const float* __restrict__ pw,
            const float* __restrict__ pbias) {
    extern __shared__ float ps[];
    float* es = ps;
    float* wsm = ps + 128 * PAD;
    const int tid = threadIdx.x;
    const int tx = tid & 15, ty = tid >> 4;
    const int c0 = blockIdx.x * 128;

    if (tid < 128) g_counts[c0 + tid] = 0;
    if (blockIdx.x == 0 && tid == 0) g_done = 0;

#pragma unroll
    for (int i = 0; i < 16; i++) {
        int f = tid + i * 256;
        int row = f >> 5;
        int c4 = f & 31;
        int sw = (((row >> 2) ^ (c4 & 7)) << 2) | (row & 3);
        float4 v = *((const float4*)(emb + (size_t)(c0 + row) * DIM) + c4);
        es[(4 * c4 + 0) * PAD + sw] = v.x;
        es[(4 * c4 + 1) * PAD + sw] = v.y;
        es[(4 * c4 + 2) * PAD + sw] = v.z;
        es[(4 * c4 + 3) * PAD + sw] = v.w;
        float4 w = *((const float4*)(pw + (size_t)row * DIM) + c4);
        wsm[(4 * c4 + 0) * PAD + sw] = w.x;
        wsm[(4 * c4 + 1) * PAD + sw] = w.y;
        wsm[(4 * c4 + 2) * PAD + sw] = w.z;
        wsm[(4 * c4 + 3) * PAD + sw] = w.w;
    }
    __syncthreads();

    float acc[8][8];
#pragma unroll
    for (int im = 0; im < 8; im++)
#pragma unroll
        for (int jn = 0; jn < 8; jn++) acc[im][jn] = 0.0f;

#pragma unroll 4
    for (int k = 0; k < 128; k++) {
        int s = (k >> 2) & 7;
        const float* er = es + k * PAD;
        const float* wr = wsm + k * PAD;
        float4 a0 = *(const float4*)(er + ((ty ^ s) << 2));
        float4 a1 = *(const float4*)(er + 64 + ((ty ^ s) << 2));
        float4 b0 = *(const float4*)(wr + ((tx ^ s) << 2));
        float4 b1 = *(const float4*)(wr + 64 + ((tx ^ s) << 2));
        float a[8] = {a0.x, a0.y, a0.z, a0.w, a1.x, a1.y, a1.z, a1.w};
        float b[8] = {b0.x, b0.y, b0.z, b0.w, b1.x, b1.y, b1.z, b1.w};
#pragma unroll
        for (int im = 0; im < 8; im++)
#pragma unroll
            for (int jn = 0; jn < 8; jn++)
                acc[im][jn] = fmaf(a[im], b[jn], acc[im][jn]);
    }

    float cnp[8];
#pragma unroll
    for (int im = 0; im < 8; im++) cnp[im] = 0.0f;

#pragma unroll
    for (int im = 0; im < 8; im++) {
        int cl = (im < 4) ? (ty * 4 + im) : (64 + ty * 4 + im - 4);
        int cg = c0 + cl;
        int tile = cg >> 6, nblk = (cg >> 3) & 7, nl = cg & 7;
#pragma unroll
        for (int jn = 0; jn < 8; jn++) {
            int d = (jn < 4) ? (tx * 4 + jn) : (64 + tx * 4 + jn - 4);
            float val = acc[im][jn] + pbias[d];
            g_codebook[(size_t)cg * DIM + d] = val;
            cnp[im] = fmaf(val, val, cnp[im]);
            int kblk = d >> 4, kin = d & 15;
            int regsel = kin >> 3, ksub = (kin & 7) >> 1, par = kin & 1;
            int lane = nl * 4 + ksub;
            size_t off = (size_t)tile * TILE_BYTES + nblk * 2048 + kblk * 256
                       + lane * 8 + regsel * 4 + par * 2;
            *(__half*)(g_cbt + off) = __float2half_rn(val);
        }
    }
#pragma unroll
    for (int im = 0; im < 8; im++) {
#pragma unroll
        for (int o = 8; o > 0; o >>= 1)
            cnp[im] += __shfl_xor_sync(0xffffffffu, cnp[im], o, 16);
    }
    if (tx == 0) {
#pragma unroll
        for (int im = 0; im < 8; im++) {
            int cl = (im < 4) ? (ty * 4 + im) : (64 + ty * 4 + im - 4);
            g_cnorm[c0 + cl] = cnp[im];
        }
    }
}

/* ---------------- fused: fp16-acc HMMA GEMM + per-lane top-2 + exact rescore + loss ---------------- */
__global__ __launch_bounds__(256, 2)
void k_gemm(const float* __restrict__ z, float* __restrict__ out) {
    extern __shared__ unsigned char smem[];
    const uint32_t sb = smem_u32(smem);
    const int tid = threadIdx.x;
    const int lane = tid & 31;
    const int warp = tid >> 5;
    const int r = lane >> 2;
    const int cc = lane & 3;
    const int m0 = blockIdx.x * BM;

    /* prologue: prefetch B tiles 0 and 1 into ring slots 0,1 */
#pragma unroll
    for (int t = 0; t < 2; t++) {
        const unsigned char* src = g_cbt + (size_t)t * TILE_BYTES;
        uint32_t dst = sb + t * TILE_BYTES;
#pragma unroll
        for (int j = 0; j < 4; j++) {
            uint32_t off = (uint32_t)(tid + j * 256) * 16;
            CP16(dst + off, src + off);
        }
        CP_COMMIT();
    }

    /* A fragments (fp16) in registers */
    uint32_t A[8][4];
    {
        const float* z0 = z + (size_t)(m0 + warp * 16 + r) * DIM;
#pragma unroll
        for (int kb = 0; kb < 8; kb++) {
#pragma unroll
            for (int q = 0; q < 4; q++) {
                const float* src = z0 + ((q & 1) ? 8 * DIM : 0) + kb * 16 + (q >> 1) * 8 + cc * 2;
                float2 v = *(const float2*)src;
                __half2 hh = __floats2half2_rn(v.x, v.y);
                A[kb][q] = *(uint32_t*)&hh;
            }
        }
    }

    /* per-lane top-2, rows a (r) and b (r+8) — this lane's 2048-code subset */
    float av0 = 3.4e38f, av1 = 3.4e38f, bv0 = 3.4e38f, bv1 = 3.4e38f;
    int ai0 = 0, ai1 = 0, bi0 = 0, bi1 = 0;

    int buf = 0, nbuf = 2;
    for (int i = 0; i < ITERS; i++) {
        CP_WAIT1();
        __syncthreads();
        if (i + 2 < ITERS) {
            const unsigned char* src = g_cbt + (size_t)(i + 2) * TILE_BYTES;
            uint32_t dst = sb + nbuf * TILE_BYTES;
#pragma unroll
            for (int j = 0; j < 4; j++) {
                uint32_t off = (uint32_t)(tid + j * 256) * 16;
                CP16(dst + off, src + off);
            }
        }
        CP_COMMIT();

        uint32_t acc[8][2];
#pragma unroll
        for (int nb = 0; nb < 8; nb++) { acc[nb][0] = 0u; acc[nb][1] = 0u; }

        const uint32_t bbase = sb + buf * TILE_BYTES + lane * 8;
#pragma unroll
        for (int kb = 0; kb < 8; kb++) {
#pragma unroll
            for (int nb = 0; nb < 8; nb++) {
                uint32_t b0, b1;
                asm volatile("ld.shared.v2.b32 {%0,%1},[%2];"
                             : "=r"(b0), "=r"(b1) : "r"(bbase + nb * 2048 + kb * 256));
                MMA_F16ACC(acc[nb], A[kb], b0, b1);
            }
        }

        const int n0i = i * 64;
#pragma unroll
        for (int nb = 0; nb < 8; nb++) {
            int n = n0i + nb * 8 + cc * 2;
            float2 cn = *(const float2*)(g_cnorm + n);
            float2 fa = __half22float2(*(__half2*)&acc[nb][0]);
            float2 fb = __half22float2(*(__half2*)&acc[nb][1]);
            float s0 = fmaf(-2.0f, fa.x, cn.x);
            float s1 = fmaf(-2.0f, fa.y, cn.y);
            float s2 = fmaf(-2.0f, fb.x, cn.x);
            float s3 = fmaf(-2.0f, fb.y, cn.y);
            INS2(av0, av1, ai0, ai1, s0, n);
            INS2(av0, av1, ai0, ai1, s1, n + 1);
            INS2(bv0, bv1, bi0, bi1, s2, n);
            INS2(bv0, bv1, bi0, bi1, s3, n + 1);
        }
        buf = (buf == 2) ? 0 : buf + 1;
        nbuf = (nbuf == 2) ? 0 : nbuf + 1;
    }

    /* ---- stash 8 candidates per token in smem (ring drained) ---- */
    CP_WAIT0();
    __syncthreads();
    int*   scand = (int*)smem;                  /* [128 tokens][8 cands] = 4KB */
    float* swsq  = (float*)(smem + 4096);
    int*   sflag = (int*)(smem + 4096 + 32);
    {
        int ta = warp * 16 + r, tb = ta + 8;
        scand[ta * 8 + cc * 2]     = ai0;
        scand[ta * 8 + cc * 2 + 1] = ai1;
        scand[tb * 8 + cc * 2]     = bi0;
        scand[tb * 8 + cc * 2 + 1] = bi1;
    }
    __syncthreads();

    /* ---- exact fp32 rescore of 8 candidates: group g=lane>>2 owns cand g,
            sub=lane&3 covers 32 dims (float4 idx sub, sub+4, ..., sub+28) ---- */
    const int g = lane >> 2;
    const int sub = lane & 3;
    float warp_sq = 0.0f;
    for (int j = 0; j < 16; j++) {
        const int tl = warp * 16 + j;
        const int t = m0 + tl;
        int cj = scand[tl * 8 + g];
        const float4* zt = (const float4*)(z + (size_t)t * DIM);
        const float4* cb = (const float4*)(g_codebook + (size_t)cj * DIM);
        float d = 0.0f;
#pragma unroll
        for (int k = 0; k < 8; k++) {
            float4 a = zt[sub + 4 * k];
            float4 b = cb[sub + 4 * k];
            d = fmaf(a.x, b.x, d);
            d = fmaf(a.y, b.y, d);
            d = fmaf(a.z, b.z, d);
            d = fmaf(a.w, b.w, d);
        }
        d += __shfl_xor_sync(0xffffffffu, d, 1);
        d += __shfl_xor_sync(0xffffffffu, d, 2);
        float bv = g_cnorm[cj] - 2.0f * d;
        int bidx = cj;
#pragma unroll
        for (int o = 4; o <= 16; o <<= 1) {
            float ov = __shfl_xor_sync(0xffffffffu, bv, o);
            int   oi = __shfl_xor_sync(0xffffffffu, bidx, o);
            if (ov < bv || (ov == bv && oi < bidx)) { bv = ov; bidx = oi; }
        }

        float4 zv = zt[lane];
        float4 c  = ((const float4*)(g_codebook + (size_t)bidx * DIM))[lane];
        float dx = c.x - zv.x, dy = c.y - zv.y, dz = c.z - zv.z, dw = c.w - zv.w;
        float4 o4;
        o4.x = zv.x + dx; o4.y = zv.y + dy; o4.z = zv.z + dz; o4.w = zv.w + dw;
        ((float4*)(out + (size_t)t * DIM))[lane] = o4;

        float sq = dx * dx + dy * dy + dz * dz + dw * dw;
#pragma unroll
        for (int o = 16; o > 0; o >>= 1) sq += __shfl_xor_sync(0xffffffffu, sq, o);
        warp_sq += sq;
        if (lane == 0) atomicAdd(&g_counts[bidx], 1);
    }
    if (lane == 0) swsq[warp] = warp_sq;
    __syncthreads();
    if (tid == 0) {
        double s = 0.0;
#pragma unroll
        for (int i = 0; i < 8; i++) s += (double)swsq[i];
        g_ssep[blockIdx.x] = s;
        __threadfence();
        unsigned int t = atomicAdd(&g_done, 1u);
        *sflag = (t == GRID_GEMM - 1) ? 1 : 0;
    }
    __syncthreads();

    /* ---- last CTA computes commit_loss + perplexity ---- */
    if (*sflag) {
        __threadfence();
        __shared__ double wd[8];
        __shared__ float wf[8];
        double sd = g_ssep[tid];
        float s = 0.0f;
        const float invT = 1.0f / (float)T_TOK;
        for (int i = tid; i < KC; i += 256) {
            float e = (float)g_counts[i] * invT;
            s += e * logf(e + 1e-8f);
        }
#pragma unroll
        for (int o = 16; o > 0; o >>= 1) {
            sd += __shfl_down_sync(0xffffffffu, sd, o);
            s  += __shfl_down_sync(0xffffffffu, s, o);
        }
        if (lane == 0) { wd[warp] = sd; wf[warp] = s; }
        __syncthreads();
        if (tid == 0) {
            double td = 0.0; float tf = 0.0f;
#pragma unroll
            for (int i = 0; i < 8; i++) { td += wd[i]; tf += wf[i]; }
            double mse = td / (double)((size_t)T_TOK * DIM);
            out[(size_t)T_TOK * DIM]     = (float)(1.25 * mse);
            out[(size_t)T_TOK * DIM + 1] = expf(-tf);
        }
    }
}

extern "C" void kernel_launch(void* const* d_in, const int* in_sizes, int n_in,
                              void* d_out, int out_size) {
    const float* z   = (const float*)d_in[0];
    const float* emb = (const float*)d_in[1];
    const float* pw  = (const float*)d_in[2];
    const float* pb  = (const float*)d_in[3];
    float* out = (float*)d_out;

    cudaFuncSetAttribute(k_proj, cudaFuncAttributeMaxDynamicSharedMemorySize, SMEM_PROJ);
    cudaFuncSetAttribute(k_gemm, cudaFuncAttributeMaxDynamicSharedMemorySize, SMEM_GEMM);

    k_proj<<<KC / 128, 256, SMEM_PROJ>>>(emb, pw, pb);
    k_gemm<<<GRID_GEMM, 256, SMEM_GEMM>>>(z, out);
}